// round 5
// baseline (speedup 1.0000x reference)
#include <cuda_runtime.h>
#include <cuda_bf16.h>
#include <cstdint>
#include <cstddef>

#define BB 32
#define TT 512
#define DD 512
#define UU 512

// ---------------------------------------------------------------------------
// Device-global scratch (no cudaMalloc allowed)
// ---------------------------------------------------------------------------
__device__ float    g_mx[(size_t)BB * TT * 3 * UU];   // x@kernel + bias
__device__ float    g_rh[BB * UU];                    // r*h exchange buffer
__device__ unsigned g_cnt[8];
__device__ unsigned g_ep[8];

__device__ __forceinline__ float hsig(float x) {
    return fminf(fmaxf(fmaf(0.2f, x, 0.5f), 0.0f), 1.0f);
}

// ---------------------------------------------------------------------------
// Kernel 1: mx = x @ kernel + bias   (M=16384, N=1536, K=512)
// ---------------------------------------------------------------------------
__global__ __launch_bounds__(256) void mx_gemm(const float* __restrict__ X,
                                               const float* __restrict__ W,
                                               const float* __restrict__ bias) {
    __shared__ float As[16][132];
    __shared__ float Bs[16][68];

    const int tid = threadIdx.x;
    const int m0  = blockIdx.y * 128;
    const int n0  = blockIdx.x * 64;
    const int tm  = tid & 15;
    const int tn  = tid >> 4;

    float acc[8][4];
#pragma unroll
    for (int i = 0; i < 8; i++)
#pragma unroll
        for (int j = 0; j < 4; j++) acc[i][j] = 0.0f;

    for (int kk = 0; kk < DD; kk += 16) {
#pragma unroll
        for (int jj = 0; jj < 2; jj++) {
            int idx = tid + jj * 256;
            int r   = idx >> 2;
            int kq  = (idx & 3) << 2;
            float4 v = *(const float4*)&X[(size_t)(m0 + r) * DD + kk + kq];
            As[kq + 0][r] = v.x;
            As[kq + 1][r] = v.y;
            As[kq + 2][r] = v.z;
            As[kq + 3][r] = v.w;
        }
        {
            int kr = tid >> 4;
            int nq = (tid & 15) << 2;
            float4 v = *(const float4*)&W[(size_t)(kk + kr) * (3 * UU) + n0 + nq];
            *(float4*)&Bs[kr][nq] = v;
        }
        __syncthreads();

#pragma unroll
        for (int k = 0; k < 16; k++) {
            float4 a0 = *(const float4*)&As[k][tm << 2];
            float4 a1 = *(const float4*)&As[k][64 + (tm << 2)];
            float4 b0 = *(const float4*)&Bs[k][tn << 2];
            float af[8] = {a0.x, a0.y, a0.z, a0.w, a1.x, a1.y, a1.z, a1.w};
            float bf[4] = {b0.x, b0.y, b0.z, b0.w};
#pragma unroll
            for (int i = 0; i < 8; i++)
#pragma unroll
                for (int j = 0; j < 4; j++) acc[i][j] = fmaf(af[i], bf[j], acc[i][j]);
        }
        __syncthreads();
    }

    float4 bv = *(const float4*)&bias[n0 + (tn << 2)];
#pragma unroll
    for (int i = 0; i < 8; i++) {
        int m = (i < 4) ? ((tm << 2) + i) : (64 + (tm << 2) + (i - 4));
        float4 o;
        o.x = acc[i][0] + bv.x;
        o.y = acc[i][1] + bv.y;
        o.z = acc[i][2] + bv.z;
        o.w = acc[i][3] + bv.w;
        *(float4*)&g_mx[(size_t)(m0 + m) * (3 * UU) + n0 + (tn << 2)] = o;
    }
}

// ===========================================================================
// GRU recurrence, register-resident Wz/Wr.
// 128 CTAs = 8 groups (x4 batches) * 16 col-CTAs (x32 cols), 512 thr, 1/SM.
// Template: CLU=true -> HW cluster-16 barrier; false -> software barrier.
// ===========================================================================
struct SMW {
    float wh[512 * 32];      // 64 KB
    float stage[4][512];     // 8 KB
    float red[4096];         // 16 KB
    float zs[128];
    float hown[128];
};
#define SMW_BYTES ((int)sizeof(SMW))

__device__ __forceinline__ void bg_sync(int bg, unsigned target) {
    __threadfence();
    __syncthreads();
    if (threadIdx.x == 0) {
        unsigned p = atomicAdd(&g_cnt[bg], 1u);
        if (p == 15u) {
            g_cnt[bg] = 0u;
            __threadfence();
            *(volatile unsigned*)&g_ep[bg] = target;
        } else {
            while (*(volatile unsigned*)&g_ep[bg] < target) { }
        }
    }
    __syncthreads();
}

#define RED2(v) do { \
    (v) += __shfl_xor_sync(0xffffffffu, (v), 8);  \
    (v) += __shfl_xor_sync(0xffffffffu, (v), 16); \
} while (0)

template <bool CLU>
__global__ __launch_bounds__(512, 1) void gru_w(const float* __restrict__ RK,
                                                float* __restrict__ out) {
    extern __shared__ char raw[];
    SMW* s = (SMW*)raw;
    const int tid = threadIdx.x;
    const int grp = blockIdx.x >> 4;     // 0..7
    const int gb0 = grp << 2;
    const int j0  = (blockIdx.x & 15) << 5;

    const int ks = tid >> 3;             // 0..63, u-range = ks*8..+7
    const int cs = tid & 7;              // 0..7, cols cs*4..+3
    const int ub = ks << 3;
    const int w  = tid >> 5;
    const int l  = tid & 31;

    // gate-reduction thread mapping (tid<256 / tid<128)
    const int gate = tid >> 7;
    const int rb   = (tid >> 5) & 3;
    const int rc   = tid & 31;

    // Wh -> SMEM (coalesced float4)
    for (int i = tid; i < (512 * 32) / 4; i += 512) {
        int f = i << 2;
        int u = f >> 5, c = f & 31;
        *(float4*)&s->wh[f] = *(const float4*)&RK[(size_t)u * 1536 + 1024 + j0 + c];
    }
    // Wz/Wr -> registers (8u x 4c each)
    float wzr[8][4], wrr[8][4];
#pragma unroll
    for (int uu = 0; uu < 8; uu++) {
        const float* bp = &RK[(size_t)(ub + uu) * 1536 + j0 + (cs << 2)];
        float4 a  = *(const float4*)bp;
        float4 b4 = *(const float4*)(bp + 512);
        wzr[uu][0] = a.x;  wzr[uu][1] = a.y;  wzr[uu][2] = a.z;  wzr[uu][3] = a.w;
        wrr[uu][0] = b4.x; wrr[uu][1] = b4.y; wrr[uu][2] = b4.z; wrr[uu][3] = b4.w;
    }

    __shared__ unsigned ep0;
    if (!CLU && tid == 0) ep0 = *(volatile unsigned*)&g_ep[grp];
    __syncthreads();
    unsigned tgt = CLU ? 0u : ep0;

    auto SYNCG = [&]() {
        if (CLU) {
            asm volatile("barrier.cluster.arrive.aligned;" ::: "memory");
            asm volatile("barrier.cluster.wait.aligned;" ::: "memory");
        } else {
            bg_sync(grp, ++tgt);
        }
    };

    // ---- t = 0 : h_prev = 0 ----
    if (tid < 128) {
        int b = tid >> 5, c = tid & 31;
        size_t mrow = (size_t)(gb0 + b) * TT * 1536;
        float z  = hsig(g_mx[mrow + j0 + c]);
        float hh = tanhf(g_mx[mrow + 1024 + j0 + c]);
        out[(size_t)(gb0 + b) * TT * UU + j0 + c] = (1.0f - z) * hh;
    }
    SYNCG();

#pragma unroll 1
    for (int t = 1; t < TT; t++) {
        // prefetch mx gate terms (hide DRAM under FMA)
        float pm1 = 0.0f, pm2 = 0.0f;
        if (tid < 256) {
            size_t mrow = ((size_t)(gb0 + rb) * TT + t) * 1536;
            pm1 = __ldcg(&g_mx[mrow + (gate << 9) + j0 + rc]);
            if (tid < 128) pm2 = __ldcg(&g_mx[mrow + 1024 + j0 + rc]);
        }

        // stage h(t-1)
        {
            int b = tid >> 7, ug = tid & 127;
            float4 v = __ldcg(
                (const float4*)(out + ((size_t)(gb0 + b) * TT + (t - 1)) * UU) + ug);
            *(float4*)&s->stage[b][ug << 2] = v;
        }
        __syncthreads();

        // ---- z pass (register weights) ----
        {
            float az[4][4];
#pragma unroll
            for (int b = 0; b < 4; b++)
#pragma unroll
                for (int c = 0; c < 4; c++) az[b][c] = 0.0f;
#pragma unroll
            for (int uu = 0; uu < 8; uu++) {
                int u = ub + uu;
                float h0 = s->stage[0][u], h1 = s->stage[1][u];
                float h2 = s->stage[2][u], h3 = s->stage[3][u];
#pragma unroll
                for (int c = 0; c < 4; c++) {
                    float wv = wzr[uu][c];
                    az[0][c] = fmaf(h0, wv, az[0][c]);
                    az[1][c] = fmaf(h1, wv, az[1][c]);
                    az[2][c] = fmaf(h2, wv, az[2][c]);
                    az[3][c] = fmaf(h3, wv, az[3][c]);
                }
            }
#pragma unroll
            for (int b = 0; b < 4; b++)
#pragma unroll
                for (int c = 0; c < 4; c++) RED2(az[b][c]);
            if (l < 8) {
#pragma unroll
                for (int b = 0; b < 4; b++)
                    *(float4*)&s->red[(w << 8) + (b << 5) + (l << 2)] =
                        make_float4(az[b][0], az[b][1], az[b][2], az[b][3]);
            }
        }
        // ---- r pass ----
        {
            float ar[4][4];
#pragma unroll
            for (int b = 0; b < 4; b++)
#pragma unroll
                for (int c = 0; c < 4; c++) ar[b][c] = 0.0f;
#pragma unroll
            for (int uu = 0; uu < 8; uu++) {
                int u = ub + uu;
                float h0 = s->stage[0][u], h1 = s->stage[1][u];
                float h2 = s->stage[2][u], h3 = s->stage[3][u];
#pragma unroll
                for (int c = 0; c < 4; c++) {
                    float wv = wrr[uu][c];
                    ar[0][c] = fmaf(h0, wv, ar[0][c]);
                    ar[1][c] = fmaf(h1, wv, ar[1][c]);
                    ar[2][c] = fmaf(h2, wv, ar[2][c]);
                    ar[3][c] = fmaf(h3, wv, ar[3][c]);
                }
            }
#pragma unroll
            for (int b = 0; b < 4; b++)
#pragma unroll
                for (int c = 0; c < 4; c++) RED2(ar[b][c]);
            if (l < 8) {
#pragma unroll
                for (int b = 0; b < 4; b++)
                    *(float4*)&s->red[(w << 8) + 128 + (b << 5) + (l << 2)] =
                        make_float4(ar[b][0], ar[b][1], ar[b][2], ar[b][3]);
            }
        }
        __syncthreads();

        // ---- gates: z -> zs/hown, r -> g_rh ----
        if (tid < 256) {
            float sum = pm1;
#pragma unroll
            for (int k = 0; k < 16; k++) sum += s->red[(k << 8) + tid];
            float hp = s->stage[rb][j0 + rc];
            if (gate == 0) {
                s->zs[(rb << 5) + rc]   = hsig(sum);
                s->hown[(rb << 5) + rc] = hp;
            } else {
                g_rh[(size_t)(gb0 + rb) * UU + j0 + rc] = hsig(sum) * hp;
            }
        }
        SYNCG();

        // stage rh
        {
            int b = tid >> 7, ug = tid & 127;
            float4 v = __ldcg((const float4*)(g_rh + (size_t)(gb0 + b) * UU) + ug);
            *(float4*)&s->stage[b][ug << 2] = v;
        }
        __syncthreads();

        // ---- h-candidate pass (Wh from SMEM, float4 rows) ----
        {
            float ah[4][4];
#pragma unroll
            for (int b = 0; b < 4; b++)
#pragma unroll
                for (int c = 0; c < 4; c++) ah[b][c] = 0.0f;
#pragma unroll
            for (int uu = 0; uu < 8; uu++) {
                int u = ub + uu;
                float4 wv = *(const float4*)&s->wh[(u << 5) + (cs << 2)];
                float h0 = s->stage[0][u], h1 = s->stage[1][u];
                float h2 = s->stage[2][u], h3 = s->stage[3][u];
                ah[0][0] = fmaf(h0, wv.x, ah[0][0]); ah[0][1] = fmaf(h0, wv.y, ah[0][1]);
                ah[0][2] = fmaf(h0, wv.z, ah[0][2]); ah[0][3] = fmaf(h0, wv.w, ah[0][3]);
                ah[1][0] = fmaf(h1, wv.x, ah[1][0]); ah[1][1] = fmaf(h1, wv.y, ah[1][1]);
                ah[1][2] = fmaf(h1, wv.z, ah[1][2]); ah[1][3] = fmaf(h1, wv.w, ah[1][3]);
                ah[2][0] = fmaf(h2, wv.x, ah[2][0]); ah[2][1] = fmaf(h2, wv.y, ah[2][1]);
                ah[2][2] = fmaf(h2, wv.z, ah[2][2]); ah[2][3] = fmaf(h2, wv.w, ah[2][3]);
                ah[3][0] = fmaf(h3, wv.x, ah[3][0]); ah[3][1] = fmaf(h3, wv.y, ah[3][1]);
                ah[3][2] = fmaf(h3, wv.z, ah[3][2]); ah[3][3] = fmaf(h3, wv.w, ah[3][3]);
            }
#pragma unroll
            for (int b = 0; b < 4; b++)
#pragma unroll
                for (int c = 0; c < 4; c++) RED2(ah[b][c]);
            if (l < 8) {
#pragma unroll
                for (int b = 0; b < 4; b++)
                    *(float4*)&s->red[(w << 7) + (b << 5) + (l << 2)] =
                        make_float4(ah[b][0], ah[b][1], ah[b][2], ah[b][3]);
            }
        }
        __syncthreads();

        // ---- final update ----
        if (tid < 128) {
            float sum = pm2;
#pragma unroll
            for (int k = 0; k < 16; k++) sum += s->red[(k << 7) + tid];
            float hh = tanhf(sum);
            float z  = s->zs[tid];
            float hp = s->hown[tid];
            out[((size_t)(gb0 + (tid >> 5)) * TT + t) * UU + j0 + (tid & 31)] =
                z * hp + (1.0f - z) * hh;
        }
        SYNCG();
    }
}

// ---------------------------------------------------------------------------
extern "C" void kernel_launch(void* const* d_in, const int* in_sizes, int n_in,
                              void* d_out, int out_size) {
    const float* x    = (const float*)d_in[0];
    const float* ker  = (const float*)d_in[1];
    const float* rk   = (const float*)d_in[2];
    const float* bias = (const float*)d_in[3];
    float* out = (float*)d_out;
    (void)in_sizes; (void)n_in; (void)out_size;

    static int mode = -1;
    if (mode < 0) {
        mode = 0;
        cudaError_t e1 = cudaFuncSetAttribute(
            gru_w<true>, cudaFuncAttributeMaxDynamicSharedMemorySize, SMW_BYTES);
        cudaError_t e2 = cudaFuncSetAttribute(
            gru_w<true>, cudaFuncAttributeNonPortableClusterSizeAllowed, 1);
        if (e1 == cudaSuccess && e2 == cudaSuccess) {
            cudaLaunchConfig_t cfg = {};
            cfg.gridDim  = dim3(128, 1, 1);
            cfg.blockDim = dim3(512, 1, 1);
            cfg.dynamicSmemBytes = SMW_BYTES;
            cudaLaunchAttribute attr[1];
            attr[0].id = cudaLaunchAttributeClusterDimension;
            attr[0].val.clusterDim.x = 16;
            attr[0].val.clusterDim.y = 1;
            attr[0].val.clusterDim.z = 1;
            cfg.attrs = attr;
            cfg.numAttrs = 1;
            int nclu = 0;
            cudaError_t e3 = cudaOccupancyMaxActiveClusters(&nclu, gru_w<true>, &cfg);
            if (e3 == cudaSuccess && nclu >= 1) mode = 1;   // groups independent: any residency is safe
        }
        cudaGetLastError();  // clear sticky probe errors
        cudaFuncSetAttribute(gru_w<false>, cudaFuncAttributeMaxDynamicSharedMemorySize,
                             SMW_BYTES);
    }

    dim3 gg(24, 128);
    mx_gemm<<<gg, 256>>>(x, ker, bias);

    if (mode == 1) {
        cudaLaunchConfig_t cfg = {};
        cfg.gridDim  = dim3(128, 1, 1);
        cfg.blockDim = dim3(512, 1, 1);
        cfg.dynamicSmemBytes = SMW_BYTES;
        cudaLaunchAttribute attr[1];
        attr[0].id = cudaLaunchAttributeClusterDimension;
        attr[0].val.clusterDim.x = 16;
        attr[0].val.clusterDim.y = 1;
        attr[0].val.clusterDim.z = 1;
        cfg.attrs = attr;
        cfg.numAttrs = 1;
        cudaLaunchKernelEx(&cfg, gru_w<true>, rk, out);
    } else {
        gru_w<false><<<128, 512, SMW_BYTES>>>(rk, out);
    }
}